// round 10
// baseline (speedup 1.0000x reference)
#include <cuda_runtime.h>
#include <cuda_bf16.h>
#include <cstdint>

#define FF  512
#define HD  64
#define NH  8
#define NC  10
#define NMAX 50000
#define EMAX 1700000
#define SCANB 256
#define NBMAX ((NMAX + SCANB - 1) / SCANB)

// -------- scratch (static device globals; no allocation allowed) ----------
static __device__ float g_h1  [NMAX*HD];
static __device__ float g_as1 [NMAX*NH];
static __device__ float g_ad1 [NMAX*NH];
static __device__ float g_x2  [NMAX*HD];
static __device__ float g_h2  [NMAX*NC];
static __device__ float g_as2 [NMAX];
static __device__ float g_ad2 [NMAX];
static __device__ int   g_cnt [NMAX];
static __device__ int   g_off [NMAX+1];
static __device__ int   g_cur [NMAX];
static __device__ int   g_csr [EMAX];
static __device__ int   g_bsum[NBMAX];
static __device__ int   g_is32;
// Precomputed W1 hi/lo bf16 pairs: [tile 0..15][n 0..63][j 0..15] contiguous
static __device__ uint32_t g_w1hi[16*64*16];
static __device__ uint32_t g_w1lo[16*64*16];

__device__ __forceinline__ uint32_t packbf(float lo16, float hi16) {
    uint32_t r;
    asm("cvt.rn.bf16x2.f32 %0, %1, %2;" : "=r"(r) : "f"(hi16), "f"(lo16));
    return r;
}
__device__ __forceinline__ uint32_t prmt_hi(uint32_t a, uint32_t b) {
    uint32_t r;   // low half = a.hi16 (even k), high half = b.hi16 (odd k)
    asm("prmt.b32 %0, %1, %2, 0x7632;" : "=r"(r) : "r"(a), "r"(b));
    return r;
}
__device__ __forceinline__ void mma_bf16(float* c, const uint32_t* a, const uint32_t* b) {
    asm volatile(
        "mma.sync.aligned.m16n8k16.row.col.f32.bf16.bf16.f32 "
        "{%0,%1,%2,%3}, {%4,%5,%6,%7}, {%8,%9}, {%0,%1,%2,%3};"
        : "+f"(c[0]), "+f"(c[1]), "+f"(c[2]), "+f"(c[3])
        : "r"(a[0]), "r"(a[1]), "r"(a[2]), "r"(a[3]), "r"(b[0]), "r"(b[1]));
}

// -------- edge dtype sniffer ----------------------------------------------
__global__ void k_detect(const long long* __restrict__ e, long long E, long long N) {
    if (blockIdx.x == 0 && threadIdx.x == 0) {
        int is32 = 0;
        long long cnt = E < 256 ? E : 256;
        for (long long i = 0; i < cnt; i++) {
            long long v = e[i];
            if (v < 0 || v >= N) { is32 = 1; break; }
        }
        g_is32 = is32;
    }
}

__global__ void k_zero(int N) {
    int i = blockIdx.x * blockDim.x + threadIdx.x;
    if (i < N) g_cnt[i] = 0;
}

// -------- one-shot W1 conversion: fp32 -> hi/lo bf16 pair tiles ------------
__global__ void k_wconv(const float* __restrict__ W) {
    int i = blockIdx.x * blockDim.x + threadIdx.x;   // 16384
    int tile = i >> 10, rem = i & 1023;
    int n = rem >> 4, j = rem & 15;
    int k = tile * 32 + 2 * j;
    float w0 = W[k * 64 + n], w1 = W[(k + 1) * 64 + n];
    uint32_t u0 = __float_as_uint(w0), u1 = __float_as_uint(w1);
    float h0 = __uint_as_float(u0 & 0xFFFF0000u);
    float h1 = __uint_as_float(u1 & 0xFFFF0000u);
    g_w1hi[i] = prmt_hi(u0, u1);
    g_w1lo[i] = packbf(w0 - h0, w1 - h1);
}

// -------- CSR build: histogram ---------------------------------------------
__global__ void k_hist(const void* __restrict__ ei, long long E, int N) {
    long long i = (long long)blockIdx.x * blockDim.x + threadIdx.x;
    long long EN = E + (long long)N;
    if (i >= EN) return;
    int d;
    if (i >= E) d = (int)(i - E);
    else if (g_is32) d = ((const int*)ei)[E + i];
    else             d = (int)((const long long*)ei)[E + i];
    atomicAdd(&g_cnt[d], 1);
}

// -------- two-level scan ---------------------------------------------------
__global__ void k_scan1(int N) {
    __shared__ int sh[SCANB];
    int t = threadIdx.x;
    int i = blockIdx.x * SCANB + t;
    int v = (i < N) ? g_cnt[i] : 0;
    sh[t] = v;
    __syncthreads();
    #pragma unroll
    for (int o = 1; o < SCANB; o <<= 1) {
        int u = (t >= o) ? sh[t - o] : 0;
        __syncthreads();
        sh[t] += u;
        __syncthreads();
    }
    if (i < N) g_off[i] = sh[t] - v;
    if (t == SCANB - 1) g_bsum[blockIdx.x] = sh[t];
}
__global__ void k_scan2(int nb) {
    __shared__ int sh[SCANB];
    int t = threadIdx.x;
    int v = (t < nb) ? g_bsum[t] : 0;
    sh[t] = v;
    __syncthreads();
    #pragma unroll
    for (int o = 1; o < SCANB; o <<= 1) {
        int u = (t >= o) ? sh[t - o] : 0;
        __syncthreads();
        sh[t] += u;
        __syncthreads();
    }
    if (t < nb) g_bsum[t] = sh[t] - v;
}
__global__ void k_scan3(int N, int total) {
    int i = blockIdx.x * blockDim.x + threadIdx.x;
    if (i < N) {
        int o = g_off[i] + g_bsum[i / SCANB];
        g_off[i] = o;
        g_cur[i] = o;
    }
    if (i == 0) g_off[N] = total;
}

// -------- CSR scatter ------------------------------------------------------
__global__ void k_scatter(const void* __restrict__ ei, long long E, int N) {
    long long i = (long long)blockIdx.x * blockDim.x + threadIdx.x;
    long long EN = E + (long long)N;
    if (i >= EN) return;
    int s, d;
    if (i >= E) { s = d = (int)(i - E); }
    else if (g_is32) { const int* p = (const int*)ei; s = p[i]; d = p[E + i]; }
    else { const long long* p = (const long long*)ei; s = (int)p[i]; d = (int)p[E + i]; }
    int pos = atomicAdd(&g_cur[d], 1);
    g_csr[pos] = s;
}

// -------- GEMM1 (tensor cores): split-bf16 (truncation), alpha1 fused ------
// C = Xhi*Whi + Xhi*Wlo + Xlo*Whi. W staged from precomputed g_w1hi/lo.
__global__ void k_gemm1(const float* __restrict__ x,
                        const float* __restrict__ a_src, const float* __restrict__ a_dst,
                        int N) {
    __shared__ uint32_t Ahi[128][20], Alo[128][20];
    __shared__ uint32_t Bhi[64][20],  Blo[64][20];
    __shared__ float sA[64], sD[64];

    int tid  = threadIdx.x;
    int lane = tid & 31;
    int warp = tid >> 5;
    int m0   = blockIdx.x * 128;
    int wrow = warp * 16;
    int g = lane >> 2, tg = lane & 3;

    if (tid < 64) { sA[tid] = a_src[tid]; sD[tid] = a_dst[tid]; }

    float c[8][4] = {};

    for (int kk = 0; kk < FF; kk += 32) {
        __syncthreads();
        // ---- X tile: truncation split, PRMT hi-pack ----
        #pragma unroll
        for (int it = 0; it < 4; it++) {
            int f   = tid + 256 * it;
            int row = f >> 3, c4 = f & 7;
            float4 v = make_float4(0.f, 0.f, 0.f, 0.f);
            if (m0 + row < N)
                v = *(const float4*)&x[(long long)(m0 + row) * FF + kk + c4 * 4];
            uint32_t ux = __float_as_uint(v.x), uy = __float_as_uint(v.y);
            uint32_t uz = __float_as_uint(v.z), uw = __float_as_uint(v.w);
            float hx = __uint_as_float(ux & 0xFFFF0000u);
            float hy = __uint_as_float(uy & 0xFFFF0000u);
            float hz = __uint_as_float(uz & 0xFFFF0000u);
            float hw = __uint_as_float(uw & 0xFFFF0000u);
            Ahi[row][c4*2+0] = prmt_hi(ux, uy);
            Ahi[row][c4*2+1] = prmt_hi(uz, uw);
            Alo[row][c4*2+0] = packbf(v.x - hx, v.y - hy);
            Alo[row][c4*2+1] = packbf(v.z - hz, v.w - hw);
        }
        // ---- W tile: direct u32 copy from precomputed layout ----
        {
            int idx = tid * 4;                 // n = idx>>4, j = idx&15 (j%4==0)
            int n = idx >> 4, j = idx & 15;
            int base = (kk >> 5) * 1024 + idx;
            uint4 h = *(const uint4*)&g_w1hi[base];
            uint4 l = *(const uint4*)&g_w1lo[base];
            *(uint4*)&Bhi[n][j] = h;
            *(uint4*)&Blo[n][j] = l;
        }
        __syncthreads();
        // ---- compute: two k16 sub-steps ----
        #pragma unroll
        for (int sub = 0; sub < 2; sub++) {
            int po = sub * 8;
            uint32_t ah[4], al[4];
            ah[0] = Ahi[wrow + g    ][po + tg];
            ah[1] = Ahi[wrow + g + 8][po + tg];
            ah[2] = Ahi[wrow + g    ][po + tg + 4];
            ah[3] = Ahi[wrow + g + 8][po + tg + 4];
            al[0] = Alo[wrow + g    ][po + tg];
            al[1] = Alo[wrow + g + 8][po + tg];
            al[2] = Alo[wrow + g    ][po + tg + 4];
            al[3] = Alo[wrow + g + 8][po + tg + 4];
            #pragma unroll
            for (int t = 0; t < 8; t++) {
                uint32_t bh[2], bl[2];
                bh[0] = Bhi[t*8 + g][po + tg];
                bh[1] = Bhi[t*8 + g][po + tg + 4];
                bl[0] = Blo[t*8 + g][po + tg];
                bl[1] = Blo[t*8 + g][po + tg + 4];
                mma_bf16(c[t], ah, bh);
                mma_bf16(c[t], ah, bl);
                mma_bf16(c[t], al, bh);
            }
        }
    }

    // ---- epilogue: h1 + fused alpha projections ----
    int row0 = m0 + wrow + g;
    int row1 = row0 + 8;
    #pragma unroll
    for (int t = 0; t < 8; t++) {
        if (row0 < N)
            *(float2*)&g_h1[row0 * 64 + t*8 + tg*2] = make_float2(c[t][0], c[t][1]);
        if (row1 < N)
            *(float2*)&g_h1[row1 * 64 + t*8 + tg*2] = make_float2(c[t][2], c[t][3]);
        float as = sA[t*8 + tg*2], as2v = sA[t*8 + tg*2 + 1];
        float ad = sD[t*8 + tg*2], ad2v = sD[t*8 + tg*2 + 1];
        float s0 = c[t][0]*as + c[t][1]*as2v;
        float d0 = c[t][0]*ad + c[t][1]*ad2v;
        float s1 = c[t][2]*as + c[t][3]*as2v;
        float d1 = c[t][2]*ad + c[t][3]*ad2v;
        #pragma unroll
        for (int o = 1; o <= 2; o <<= 1) {
            s0 += __shfl_xor_sync(0xffffffffu, s0, o);
            d0 += __shfl_xor_sync(0xffffffffu, d0, o);
            s1 += __shfl_xor_sync(0xffffffffu, s1, o);
            d1 += __shfl_xor_sync(0xffffffffu, d1, o);
        }
        if (tg == 0) {
            if (row0 < N) { g_as1[row0 * 8 + t] = s0; g_ad1[row0 * 8 + t] = d0; }
            if (row1 < N) { g_as1[row1 * 8 + t] = s1; g_ad1[row1 * 8 + t] = d1; }
        }
    }
}

// -------- aggregation layer 1 (warp per dst, CSR, no atomics) --------------
__global__ void k_agg1(const float* __restrict__ b1, int N) {
    int d = (blockIdx.x * blockDim.x + threadIdx.x) >> 5;
    int lane = threadIdx.x & 31;
    if (d >= N) return;
    int beg = g_off[d], end = g_off[d + 1];
    float ad_l = (lane < NH) ? g_ad1[d * NH + lane] : 0.f;
    float accx = 0.f, accy = 0.f, den = 0.f;
    for (int i = beg; i < end; i++) {
        int s = g_csr[i];
        float w = 0.f;
        if (lane < NH) {
            float e = g_as1[s * NH + lane] + ad_l;
            e = e > 0.f ? e : 0.2f * e;
            w = __expf(e);
            den += w;
        }
        float wl = __shfl_sync(0xffffffffu, w, lane >> 2);
        float2 hv = *(const float2*)&g_h1[s * 64 + lane * 2];
        accx += wl * hv.x;
        accy += wl * hv.y;
    }
    float denl = __shfl_sync(0xffffffffu, den, lane >> 2);
    float v0 = accx / denl + b1[2 * lane];
    float v1 = accy / denl + b1[2 * lane + 1];
    v0 = v0 > 0.f ? v0 : expm1f(v0);
    v1 = v1 > 0.f ? v1 : expm1f(v1);
    *(float2*)&g_x2[d * 64 + 2 * lane] = make_float2(v0, v1);
}

// -------- GEMM2 + alpha projections layer 2 --------------------------------
__global__ void k_gemm2(const float* __restrict__ W2,
                        const float* __restrict__ a_src2,
                        const float* __restrict__ a_dst2, int N) {
    int wid = (blockIdx.x * blockDim.x + threadIdx.x) >> 5;
    int lane = threadIdx.x & 31;
    if (wid >= N) return;
    float v0 = g_x2[wid * 64 + lane];
    float v1 = g_x2[wid * 64 + 32 + lane];
    float asum = 0.f, adsum = 0.f;
    #pragma unroll
    for (int c = 0; c < NC; c++) {
        float s = v0 * W2[lane * NC + c] + v1 * W2[(lane + 32) * NC + c];
        #pragma unroll
        for (int o = 16; o; o >>= 1) s += __shfl_down_sync(0xffffffffu, s, o);
        if (lane == 0) {
            g_h2[wid * NC + c] = s;
            asum  += s * a_src2[c];
            adsum += s * a_dst2[c];
        }
    }
    if (lane == 0) { g_as2[wid] = asum; g_ad2[wid] = adsum; }
}

// -------- aggregation layer 2 ----------------------------------------------
__global__ void k_agg2(const float* __restrict__ b2, float* __restrict__ out, int N) {
    int d = (blockIdx.x * blockDim.x + threadIdx.x) >> 5;
    int lane = threadIdx.x & 31;
    if (d >= N) return;
    int beg = g_off[d], end = g_off[d + 1];
    float ad_d = g_ad2[d];
    float acc[NC] = {};
    float den = 0.f;
    for (int i = beg + lane; i < end; i += 32) {
        int s = g_csr[i];
        float e = g_as2[s] + ad_d;
        e = e > 0.f ? e : 0.2f * e;
        float w = __expf(e);
        den += w;
        const float* hp = &g_h2[s * NC];
        #pragma unroll
        for (int c = 0; c < NC; c++) acc[c] += w * hp[c];
    }
    #pragma unroll
    for (int o = 16; o; o >>= 1) {
        den += __shfl_down_sync(0xffffffffu, den, o);
        #pragma unroll
        for (int c = 0; c < NC; c++)
            acc[c] += __shfl_down_sync(0xffffffffu, acc[c], o);
    }
    if (lane == 0) {
        float inv = 1.f / den;
        float v[NC], m = -1e30f;
        #pragma unroll
        for (int c = 0; c < NC; c++) {
            v[c] = acc[c] * inv + b2[c];
            m = fmaxf(m, v[c]);
        }
        float ssum = 0.f;
        #pragma unroll
        for (int c = 0; c < NC; c++) ssum += __expf(v[c] - m);
        float l = __logf(ssum);
        #pragma unroll
        for (int c = 0; c < NC; c++) out[d * NC + c] = v[c] - m - l;
    }
}

// ---------------------------------------------------------------------------
extern "C" void kernel_launch(void* const* d_in, const int* in_sizes, int n_in,
                              void* d_out, int out_size) {
    const float* x   = (const float*)d_in[0];
    const void*  ei  = d_in[1];
    const float* W1  = (const float*)d_in[2];
    const float* as1 = (const float*)d_in[3];
    const float* ad1 = (const float*)d_in[4];
    const float* b1  = (const float*)d_in[5];
    const float* W2  = (const float*)d_in[6];
    const float* as2 = (const float*)d_in[7];
    const float* ad2 = (const float*)d_in[8];
    const float* b2  = (const float*)d_in[9];

    int       N  = in_sizes[0] / FF;
    long long E  = (long long)in_sizes[1] / 2;
    long long EN = E + (long long)N;
    int nb = (N + SCANB - 1) / SCANB;
    float* out = (float*)d_out;

    cudaStream_t s1 = 0;
    cudaEvent_t ev0 = 0, ev1 = 0;
    bool forked =
        cudaStreamCreateWithFlags(&s1, cudaStreamNonBlocking) == cudaSuccess &&
        cudaEventCreateWithFlags(&ev0, cudaEventDisableTiming) == cudaSuccess &&
        cudaEventCreateWithFlags(&ev1, cudaEventDisableTiming) == cudaSuccess;

    if (forked) forked = cudaEventRecord(ev0, 0) == cudaSuccess &&
                         cudaStreamWaitEvent(s1, ev0, 0) == cudaSuccess;

    cudaStream_t cs = forked ? s1 : 0;

    // ---- branch A: CSR build (edge_index only) ----
    k_detect<<<1, 32, 0, cs>>>((const long long*)ei, E, N);
    k_zero<<<(N + 255) / 256, 256, 0, cs>>>(N);
    k_hist<<<(unsigned)((EN + 255) / 256), 256, 0, cs>>>(ei, E, N);
    k_scan1<<<nb, SCANB, 0, cs>>>(N);
    k_scan2<<<1, SCANB, 0, cs>>>(nb);
    k_scan3<<<nb, SCANB, 0, cs>>>(N, (int)EN);
    k_scatter<<<(unsigned)((EN + 255) / 256), 256, 0, cs>>>(ei, E, N);
    if (forked) forked = cudaEventRecord(ev1, s1) == cudaSuccess;

    // ---- branch B: W conversion + projection GEMM (x, W1 only) ----
    k_wconv<<<64, 256>>>(W1);
    k_gemm1<<<(N + 127) / 128, 256>>>(x, as1, ad1, N);

    // ---- join + tail ----
    if (forked) cudaStreamWaitEvent(0, ev1, 0);

    k_agg1<<<(unsigned)(((long long)N * 32 + 255) / 256), 256>>>(b1, N);
    k_gemm2<<<(unsigned)(((long long)N * 32 + 255) / 256), 256>>>(W2, as2, ad2, N);
    k_agg2<<<(unsigned)(((long long)N * 32 + 255) / 256), 256>>>(b2, out, N);
    // Streams/events intentionally not destroyed (illegal mid-capture;
    // host-side handles only, O(1) calls, no device memory involved).
}

// round 11
// speedup vs baseline: 1.1234x; 1.1234x over previous
#include <cuda_runtime.h>
#include <cuda_bf16.h>
#include <cstdint>

#define FF  512
#define HD  64
#define NH  8
#define NC  10
#define NMAX 50000
#define EMAX 1700000
#define SCANB 256
#define NBMAX ((NMAX + SCANB - 1) / SCANB)

// -------- scratch (static device globals; no allocation allowed) ----------
static __device__ float g_h1  [NMAX*HD];
static __device__ float g_as1 [NMAX*NH];
static __device__ float g_ad1 [NMAX*NH];
static __device__ float g_x2  [NMAX*HD];
static __device__ float g_h2  [NMAX*NC];
static __device__ float g_as2 [NMAX];
static __device__ float g_ad2 [NMAX];
static __device__ int   g_cnt [NMAX];
static __device__ int   g_off [NMAX+1];
static __device__ int   g_cur [NMAX];
static __device__ int   g_csr [EMAX];
static __device__ int   g_bsum[NBMAX];
static __device__ int   g_is32;

__device__ __forceinline__ uint32_t packbf(float lo16, float hi16) {
    uint32_t r;
    asm("cvt.rn.bf16x2.f32 %0, %1, %2;" : "=r"(r) : "f"(hi16), "f"(lo16));
    return r;
}
__device__ __forceinline__ void mma_bf16(float* c, const uint32_t* a, const uint32_t* b) {
    asm volatile(
        "mma.sync.aligned.m16n8k16.row.col.f32.bf16.bf16.f32 "
        "{%0,%1,%2,%3}, {%4,%5,%6,%7}, {%8,%9}, {%0,%1,%2,%3};"
        : "+f"(c[0]), "+f"(c[1]), "+f"(c[2]), "+f"(c[3])
        : "r"(a[0]), "r"(a[1]), "r"(a[2]), "r"(a[3]), "r"(b[0]), "r"(b[1]));
}

// -------- zero + edge dtype sniffer (merged) --------------------------------
__global__ void k_zero(const long long* __restrict__ e, long long E, long long N) {
    int i = blockIdx.x * blockDim.x + threadIdx.x;
    if (i < (int)N) g_cnt[i] = 0;
    if (blockIdx.x == 0 && threadIdx.x == 0) {
        int is32 = 0;
        long long cnt = E < 256 ? E : 256;
        for (long long j = 0; j < cnt; j++) {
            long long v = e[j];
            if (v < 0 || v >= N) { is32 = 1; break; }
        }
        g_is32 = is32;
    }
}

// -------- CSR histogram -----------------------------------------------------
__global__ void k_hist(const void* __restrict__ ei, long long E, int N) {
    long long i = (long long)blockIdx.x * blockDim.x + threadIdx.x;
    long long EN = E + (long long)N;
    if (i >= EN) return;
    int d;
    if (i >= E) d = (int)(i - E);
    else if (g_is32) d = ((const int*)ei)[E + i];
    else             d = (int)((const long long*)ei)[E + i];
    atomicAdd(&g_cnt[d], 1);
}

// -------- scan level 1: block-local prefix + block totals -------------------
__global__ void k_scan1(int N) {
    __shared__ int sh[SCANB];
    int t = threadIdx.x;
    int i = blockIdx.x * SCANB + t;
    int v = (i < N) ? g_cnt[i] : 0;
    sh[t] = v;
    __syncthreads();
    #pragma unroll
    for (int o = 1; o < SCANB; o <<= 1) {
        int u = (t >= o) ? sh[t - o] : 0;
        __syncthreads();
        sh[t] += u;
        __syncthreads();
    }
    if (i < N) g_off[i] = sh[t] - v;
    if (t == SCANB - 1) g_bsum[blockIdx.x] = sh[t];
}

// -------- scan level 2+3 merged: each block reduces its prefix base ---------
__global__ void k_scan3(int N, int total, int nb) {
    __shared__ int sh[SCANB];
    int t = threadIdx.x;
    // sum of bsums with index < blockIdx.x (nb <= 256)
    int v = (t < nb && t < blockIdx.x) ? g_bsum[t] : 0;
    sh[t] = v;
    __syncthreads();
    #pragma unroll
    for (int o = SCANB / 2; o; o >>= 1) {
        if (t < o) sh[t] += sh[t + o];
        __syncthreads();
    }
    int base = sh[0];
    int i = blockIdx.x * SCANB + t;
    if (i < N) {
        int o = g_off[i] + base;
        g_off[i] = o;
        g_cur[i] = o;
    }
    if (i == 0) g_off[N] = total;
}

// -------- CSR scatter -------------------------------------------------------
__global__ void k_scatter(const void* __restrict__ ei, long long E, int N) {
    long long i = (long long)blockIdx.x * blockDim.x + threadIdx.x;
    long long EN = E + (long long)N;
    if (i >= EN) return;
    int s, d;
    if (i >= E) { s = d = (int)(i - E); }
    else if (g_is32) { const int* p = (const int*)ei; s = p[i]; d = p[E + i]; }
    else { const long long* p = (const long long*)ei; s = (int)p[i]; d = (int)p[E + i]; }
    int pos = atomicAdd(&g_cur[d], 1);
    g_csr[pos] = s;
}

// -------- GEMM1 (tensor cores): split-bf16, double-buffered, alpha1 fused ---
// C = Xhi*Whi + Xhi*Wlo + Xlo*Whi (fp32 accum). Next X/W tiles prefetched
// into registers during the MMA section to hide global-load latency.
__global__ void k_gemm1(const float* __restrict__ x, const float* __restrict__ W,
                        const float* __restrict__ a_src, const float* __restrict__ a_dst,
                        int N) {
    __shared__ uint32_t Ahi[128][20], Alo[128][20];
    __shared__ uint32_t Bhi[64][20],  Blo[64][20];
    __shared__ float sA[64], sD[64];

    int tid  = threadIdx.x;
    int lane = tid & 31;
    int warp = tid >> 5;
    int m0   = blockIdx.x * 128;
    int wrow = warp * 16;
    int g = lane >> 2, tg = lane & 3;

    if (tid < 64) { sA[tid] = a_src[tid]; sD[tid] = a_dst[tid]; }

    float c[8][4] = {};

    // prefetch tile 0 (X and W) into registers
    float4 vc[4];
    #pragma unroll
    for (int it = 0; it < 4; it++) {
        int f = tid + 256 * it, row = f >> 3, c4 = f & 7;
        vc[it] = make_float4(0.f, 0.f, 0.f, 0.f);
        if (m0 + row < N)
            vc[it] = *(const float4*)&x[(long long)(m0 + row) * FF + c4 * 4];
    }
    int wj = tid >> 4, wn4 = tid & 15;
    float4 wc0 = *(const float4*)&W[(2 * wj)     * 64 + wn4 * 4];
    float4 wc1 = *(const float4*)&W[(2 * wj + 1) * 64 + wn4 * 4];

    for (int kk = 0; kk < FF; kk += 32) {
        __syncthreads();   // smem free from previous compute
        // ---- convert current X regs -> hi/lo smem ----
        #pragma unroll
        for (int it = 0; it < 4; it++) {
            int f = tid + 256 * it, row = f >> 3, c4 = f & 7;
            float4 v = vc[it];
            float hx = __bfloat162float(__float2bfloat16(v.x));
            float hy = __bfloat162float(__float2bfloat16(v.y));
            float hz = __bfloat162float(__float2bfloat16(v.z));
            float hw = __bfloat162float(__float2bfloat16(v.w));
            Ahi[row][c4*2+0] = packbf(hx, hy);
            Ahi[row][c4*2+1] = packbf(hz, hw);
            Alo[row][c4*2+0] = packbf(v.x - hx, v.y - hy);
            Alo[row][c4*2+1] = packbf(v.z - hz, v.w - hw);
        }
        // ---- convert current W regs -> hi/lo smem ----
        {
            const float e0[4] = {wc0.x, wc0.y, wc0.z, wc0.w};
            const float e1[4] = {wc1.x, wc1.y, wc1.z, wc1.w};
            #pragma unroll
            for (int i = 0; i < 4; i++) {
                float h0 = __bfloat162float(__float2bfloat16(e0[i]));
                float h1 = __bfloat162float(__float2bfloat16(e1[i]));
                Bhi[wn4*4 + i][wj] = packbf(h0, h1);
                Blo[wn4*4 + i][wj] = packbf(e0[i] - h0, e1[i] - h1);
            }
        }
        __syncthreads();
        // ---- prefetch next tiles (loads in flight during MMA section) ----
        float4 vn[4], wn0, wn1;
        bool more = (kk + 32 < FF);
        if (more) {
            #pragma unroll
            for (int it = 0; it < 4; it++) {
                int f = tid + 256 * it, row = f >> 3, c4 = f & 7;
                vn[it] = make_float4(0.f, 0.f, 0.f, 0.f);
                if (m0 + row < N)
                    vn[it] = *(const float4*)&x[(long long)(m0 + row) * FF + kk + 32 + c4 * 4];
            }
            wn0 = *(const float4*)&W[(kk + 32 + 2 * wj)     * 64 + wn4 * 4];
            wn1 = *(const float4*)&W[(kk + 32 + 2 * wj + 1) * 64 + wn4 * 4];
        }
        // ---- compute: two k16 sub-steps ----
        #pragma unroll
        for (int sub = 0; sub < 2; sub++) {
            int po = sub * 8;
            uint32_t ah[4], al[4];
            ah[0] = Ahi[wrow + g    ][po + tg];
            ah[1] = Ahi[wrow + g + 8][po + tg];
            ah[2] = Ahi[wrow + g    ][po + tg + 4];
            ah[3] = Ahi[wrow + g + 8][po + tg + 4];
            al[0] = Alo[wrow + g    ][po + tg];
            al[1] = Alo[wrow + g + 8][po + tg];
            al[2] = Alo[wrow + g    ][po + tg + 4];
            al[3] = Alo[wrow + g + 8][po + tg + 4];
            #pragma unroll
            for (int t = 0; t < 8; t++) {
                uint32_t bh[2], bl[2];
                bh[0] = Bhi[t*8 + g][po + tg];
                bh[1] = Bhi[t*8 + g][po + tg + 4];
                bl[0] = Blo[t*8 + g][po + tg];
                bl[1] = Blo[t*8 + g][po + tg + 4];
                mma_bf16(c[t], ah, bh);
                mma_bf16(c[t], ah, bl);
                mma_bf16(c[t], al, bh);
            }
        }
        if (more) {
            #pragma unroll
            for (int it = 0; it < 4; it++) vc[it] = vn[it];
            wc0 = wn0; wc1 = wn1;
        }
    }

    // ---- epilogue: h1 + fused alpha projections ----
    int row0 = m0 + wrow + g;
    int row1 = row0 + 8;
    #pragma unroll
    for (int t = 0; t < 8; t++) {
        if (row0 < N)
            *(float2*)&g_h1[row0 * 64 + t*8 + tg*2] = make_float2(c[t][0], c[t][1]);
        if (row1 < N)
            *(float2*)&g_h1[row1 * 64 + t*8 + tg*2] = make_float2(c[t][2], c[t][3]);
        float as = sA[t*8 + tg*2], as2v = sA[t*8 + tg*2 + 1];
        float ad = sD[t*8 + tg*2], ad2v = sD[t*8 + tg*2 + 1];
        float s0 = c[t][0]*as + c[t][1]*as2v;
        float d0 = c[t][0]*ad + c[t][1]*ad2v;
        float s1 = c[t][2]*as + c[t][3]*as2v;
        float d1 = c[t][2]*ad + c[t][3]*ad2v;
        #pragma unroll
        for (int o = 1; o <= 2; o <<= 1) {
            s0 += __shfl_xor_sync(0xffffffffu, s0, o);
            d0 += __shfl_xor_sync(0xffffffffu, d0, o);
            s1 += __shfl_xor_sync(0xffffffffu, s1, o);
            d1 += __shfl_xor_sync(0xffffffffu, d1, o);
        }
        if (tg == 0) {
            if (row0 < N) { g_as1[row0 * 8 + t] = s0; g_ad1[row0 * 8 + t] = d0; }
            if (row1 < N) { g_as1[row1 * 8 + t] = s1; g_ad1[row1 * 8 + t] = d1; }
        }
    }
}

// -------- aggregation layer 1 (warp per dst, CSR, no atomics) --------------
__global__ void k_agg1(const float* __restrict__ b1, int N) {
    int d = (blockIdx.x * blockDim.x + threadIdx.x) >> 5;
    int lane = threadIdx.x & 31;
    if (d >= N) return;
    int beg = g_off[d], end = g_off[d + 1];
    float ad_l = (lane < NH) ? g_ad1[d * NH + lane] : 0.f;
    float accx = 0.f, accy = 0.f, den = 0.f;
    for (int i = beg; i < end; i++) {
        int s = g_csr[i];
        float w = 0.f;
        if (lane < NH) {
            float e = g_as1[s * NH + lane] + ad_l;
            e = e > 0.f ? e : 0.2f * e;
            w = __expf(e);
            den += w;
        }
        float wl = __shfl_sync(0xffffffffu, w, lane >> 2);
        float2 hv = *(const float2*)&g_h1[s * 64 + lane * 2];
        accx += wl * hv.x;
        accy += wl * hv.y;
    }
    float denl = __shfl_sync(0xffffffffu, den, lane >> 2);
    float v0 = accx / denl + b1[2 * lane];
    float v1 = accy / denl + b1[2 * lane + 1];
    v0 = v0 > 0.f ? v0 : expm1f(v0);
    v1 = v1 > 0.f ? v1 : expm1f(v1);
    *(float2*)&g_x2[d * 64 + 2 * lane] = make_float2(v0, v1);
}

// -------- GEMM2 + alpha projections layer 2 ---------------------------------
__global__ void k_gemm2(const float* __restrict__ W2,
                        const float* __restrict__ a_src2,
                        const float* __restrict__ a_dst2, int N) {
    int wid = (blockIdx.x * blockDim.x + threadIdx.x) >> 5;
    int lane = threadIdx.x & 31;
    if (wid >= N) return;
    float v0 = g_x2[wid * 64 + lane];
    float v1 = g_x2[wid * 64 + 32 + lane];
    float asum = 0.f, adsum = 0.f;
    #pragma unroll
    for (int c = 0; c < NC; c++) {
        float s = v0 * W2[lane * NC + c] + v1 * W2[(lane + 32) * NC + c];
        #pragma unroll
        for (int o = 16; o; o >>= 1) s += __shfl_down_sync(0xffffffffu, s, o);
        if (lane == 0) {
            g_h2[wid * NC + c] = s;
            asum  += s * a_src2[c];
            adsum += s * a_dst2[c];
        }
    }
    if (lane == 0) { g_as2[wid] = asum; g_ad2[wid] = adsum; }
}

// -------- aggregation layer 2 -----------------------------------------------
__global__ void k_agg2(const float* __restrict__ b2, float* __restrict__ out, int N) {
    int d = (blockIdx.x * blockDim.x + threadIdx.x) >> 5;
    int lane = threadIdx.x & 31;
    if (d >= N) return;
    int beg = g_off[d], end = g_off[d + 1];
    float ad_d = g_ad2[d];
    float acc[NC] = {};
    float den = 0.f;
    for (int i = beg + lane; i < end; i += 32) {
        int s = g_csr[i];
        float e = g_as2[s] + ad_d;
        e = e > 0.f ? e : 0.2f * e;
        float w = __expf(e);
        den += w;
        const float* hp = &g_h2[s * NC];
        #pragma unroll
        for (int c = 0; c < NC; c++) acc[c] += w * hp[c];
    }
    #pragma unroll
    for (int o = 16; o; o >>= 1) {
        den += __shfl_down_sync(0xffffffffu, den, o);
        #pragma unroll
        for (int c = 0; c < NC; c++)
            acc[c] += __shfl_down_sync(0xffffffffu, acc[c], o);
    }
    if (lane == 0) {
        float inv = 1.f / den;
        float v[NC], m = -1e30f;
        #pragma unroll
        for (int c = 0; c < NC; c++) {
            v[c] = acc[c] * inv + b2[c];
            m = fmaxf(m, v[c]);
        }
        float ssum = 0.f;
        #pragma unroll
        for (int c = 0; c < NC; c++) ssum += __expf(v[c] - m);
        float l = __logf(ssum);
        #pragma unroll
        for (int c = 0; c < NC; c++) out[d * NC + c] = v[c] - m - l;
    }
}

// ---------------------------------------------------------------------------
extern "C" void kernel_launch(void* const* d_in, const int* in_sizes, int n_in,
                              void* d_out, int out_size) {
    const float* x   = (const float*)d_in[0];
    const void*  ei  = d_in[1];
    const float* W1  = (const float*)d_in[2];
    const float* as1 = (const float*)d_in[3];
    const float* ad1 = (const float*)d_in[4];
    const float* b1  = (const float*)d_in[5];
    const float* W2  = (const float*)d_in[6];
    const float* as2 = (const float*)d_in[7];
    const float* ad2 = (const float*)d_in[8];
    const float* b2  = (const float*)d_in[9];

    int       N  = in_sizes[0] / FF;
    long long E  = (long long)in_sizes[1] / 2;
    long long EN = E + (long long)N;
    int nb = (N + SCANB - 1) / SCANB;
    float* out = (float*)d_out;

    cudaStream_t s1 = 0;
    cudaEvent_t ev0 = 0, ev1 = 0;
    bool forked =
        cudaStreamCreateWithFlags(&s1, cudaStreamNonBlocking) == cudaSuccess &&
        cudaEventCreateWithFlags(&ev0, cudaEventDisableTiming) == cudaSuccess &&
        cudaEventCreateWithFlags(&ev1, cudaEventDisableTiming) == cudaSuccess;

    if (forked) forked = cudaEventRecord(ev0, 0) == cudaSuccess &&
                         cudaStreamWaitEvent(s1, ev0, 0) == cudaSuccess;

    cudaStream_t cs = forked ? s1 : 0;

    // ---- branch A: CSR build (edge_index only) ----
    k_zero<<<(N + 255) / 256, 256, 0, cs>>>((const long long*)ei, E, N);
    k_hist<<<(unsigned)((EN + 255) / 256), 256, 0, cs>>>(ei, E, N);
    k_scan1<<<nb, SCANB, 0, cs>>>(N);
    k_scan3<<<nb, SCANB, 0, cs>>>(N, (int)EN, nb);
    k_scatter<<<(unsigned)((EN + 255) / 256), 256, 0, cs>>>(ei, E, N);
    if (forked) forked = cudaEventRecord(ev1, s1) == cudaSuccess;

    // ---- branch B: projection GEMM (x, W1 only) ----
    k_gemm1<<<(N + 127) / 128, 256>>>(x, W1, as1, ad1, N);

    // ---- join + tail ----
    if (forked) cudaStreamWaitEvent(0, ev1, 0);

    k_agg1<<<(unsigned)(((long long)N * 32 + 255) / 256), 256>>>(b1, N);
    k_gemm2<<<(unsigned)(((long long)N * 32 + 255) / 256), 256>>>(W2, as2, ad2, N);
    k_agg2<<<(unsigned)(((long long)N * 32 + 255) / 256), 256>>>(b2, out, N);
    // Streams/events intentionally not destroyed (illegal mid-capture;
    // host-side handles only, O(1) calls, no device memory involved).
}

// round 12
// speedup vs baseline: 1.1504x; 1.0240x over previous
#include <cuda_runtime.h>
#include <cuda_bf16.h>
#include <cstdint>

#define FF  512
#define HD  64
#define NH  8
#define NC  10
#define NMAX 50000
#define EMAX 1700000
#define SCANB 256
#define NBMAX ((NMAX + SCANB - 1) / SCANB)

// -------- scratch (static device globals; no allocation allowed) ----------
static __device__ float g_h1  [NMAX*HD];
static __device__ float g_as1 [NMAX*NH];
static __device__ float g_ad1 [NMAX*NH];
static __device__ float g_x2  [NMAX*HD];
static __device__ float g_h2p [NMAX*12];   // padded: h2[0..9], slot10 = a_src2·h2
static __device__ float g_ad2 [NMAX];
static __device__ int   g_cnt [NMAX];
static __device__ int   g_off [NMAX+1];
static __device__ int   g_cur [NMAX];
static __device__ int   g_csr [EMAX];
static __device__ int   g_bsum[NBMAX];
static __device__ int   g_is32;

__device__ __forceinline__ uint32_t packbf(float lo16, float hi16) {
    uint32_t r;
    asm("cvt.rn.bf16x2.f32 %0, %1, %2;" : "=r"(r) : "f"(hi16), "f"(lo16));
    return r;
}
__device__ __forceinline__ void mma_bf16(float* c, const uint32_t* a, const uint32_t* b) {
    asm volatile(
        "mma.sync.aligned.m16n8k16.row.col.f32.bf16.bf16.f32 "
        "{%0,%1,%2,%3}, {%4,%5,%6,%7}, {%8,%9}, {%0,%1,%2,%3};"
        : "+f"(c[0]), "+f"(c[1]), "+f"(c[2]), "+f"(c[3])
        : "r"(a[0]), "r"(a[1]), "r"(a[2]), "r"(a[3]), "r"(b[0]), "r"(b[1]));
}

// -------- zero + edge dtype sniffer (merged) --------------------------------
__global__ void k_zero(const long long* __restrict__ e, long long E, long long N) {
    int i = blockIdx.x * blockDim.x + threadIdx.x;
    if (i < (int)N) g_cnt[i] = 0;
    if (blockIdx.x == 0 && threadIdx.x == 0) {
        int is32 = 0;
        long long cnt = E < 256 ? E : 256;
        for (long long j = 0; j < cnt; j++) {
            long long v = e[j];
            if (v < 0 || v >= N) { is32 = 1; break; }
        }
        g_is32 = is32;
    }
}

// -------- CSR histogram -----------------------------------------------------
__global__ void k_hist(const void* __restrict__ ei, long long E, int N) {
    long long i = (long long)blockIdx.x * blockDim.x + threadIdx.x;
    long long EN = E + (long long)N;
    if (i >= EN) return;
    int d;
    if (i >= E) d = (int)(i - E);
    else if (g_is32) d = ((const int*)ei)[E + i];
    else             d = (int)((const long long*)ei)[E + i];
    atomicAdd(&g_cnt[d], 1);
}

// -------- scan level 1 ------------------------------------------------------
__global__ void k_scan1(int N) {
    __shared__ int sh[SCANB];
    int t = threadIdx.x;
    int i = blockIdx.x * SCANB + t;
    int v = (i < N) ? g_cnt[i] : 0;
    sh[t] = v;
    __syncthreads();
    #pragma unroll
    for (int o = 1; o < SCANB; o <<= 1) {
        int u = (t >= o) ? sh[t - o] : 0;
        __syncthreads();
        sh[t] += u;
        __syncthreads();
    }
    if (i < N) g_off[i] = sh[t] - v;
    if (t == SCANB - 1) g_bsum[blockIdx.x] = sh[t];
}

// -------- scan level 2+3 merged ---------------------------------------------
__global__ void k_scan3(int N, int total, int nb) {
    __shared__ int sh[SCANB];
    int t = threadIdx.x;
    int v = (t < nb && t < blockIdx.x) ? g_bsum[t] : 0;
    sh[t] = v;
    __syncthreads();
    #pragma unroll
    for (int o = SCANB / 2; o; o >>= 1) {
        if (t < o) sh[t] += sh[t + o];
        __syncthreads();
    }
    int base = sh[0];
    int i = blockIdx.x * SCANB + t;
    if (i < N) {
        int o = g_off[i] + base;
        g_off[i] = o;
        g_cur[i] = o;
    }
    if (i == 0) g_off[N] = total;
}

// -------- CSR scatter -------------------------------------------------------
__global__ void k_scatter(const void* __restrict__ ei, long long E, int N) {
    long long i = (long long)blockIdx.x * blockDim.x + threadIdx.x;
    long long EN = E + (long long)N;
    if (i >= EN) return;
    int s, d;
    if (i >= E) { s = d = (int)(i - E); }
    else if (g_is32) { const int* p = (const int*)ei; s = p[i]; d = p[E + i]; }
    else { const long long* p = (const long long*)ei; s = (int)p[i]; d = (int)p[E + i]; }
    int pos = atomicAdd(&g_cur[d], 1);
    g_csr[pos] = s;
}

// -------- GEMM1 (tensor cores): split-bf16, double-buffered, alpha1 fused ---
__global__ void k_gemm1(const float* __restrict__ x, const float* __restrict__ W,
                        const float* __restrict__ a_src, const float* __restrict__ a_dst,
                        int N) {
    __shared__ uint32_t Ahi[128][20], Alo[128][20];
    __shared__ uint32_t Bhi[64][20],  Blo[64][20];
    __shared__ float sA[64], sD[64];

    int tid  = threadIdx.x;
    int lane = tid & 31;
    int warp = tid >> 5;
    int m0   = blockIdx.x * 128;
    int wrow = warp * 16;
    int g = lane >> 2, tg = lane & 3;

    if (tid < 64) { sA[tid] = a_src[tid]; sD[tid] = a_dst[tid]; }

    float c[8][4] = {};

    float4 vc[4];
    #pragma unroll
    for (int it = 0; it < 4; it++) {
        int f = tid + 256 * it, row = f >> 3, c4 = f & 7;
        vc[it] = make_float4(0.f, 0.f, 0.f, 0.f);
        if (m0 + row < N)
            vc[it] = *(const float4*)&x[(long long)(m0 + row) * FF + c4 * 4];
    }
    int wj = tid >> 4, wn4 = tid & 15;
    float4 wc0 = *(const float4*)&W[(2 * wj)     * 64 + wn4 * 4];
    float4 wc1 = *(const float4*)&W[(2 * wj + 1) * 64 + wn4 * 4];

    for (int kk = 0; kk < FF; kk += 32) {
        __syncthreads();
        #pragma unroll
        for (int it = 0; it < 4; it++) {
            int f = tid + 256 * it, row = f >> 3, c4 = f & 7;
            float4 v = vc[it];
            float hx = __bfloat162float(__float2bfloat16(v.x));
            float hy = __bfloat162float(__float2bfloat16(v.y));
            float hz = __bfloat162float(__float2bfloat16(v.z));
            float hw = __bfloat162float(__float2bfloat16(v.w));
            Ahi[row][c4*2+0] = packbf(hx, hy);
            Ahi[row][c4*2+1] = packbf(hz, hw);
            Alo[row][c4*2+0] = packbf(v.x - hx, v.y - hy);
            Alo[row][c4*2+1] = packbf(v.z - hz, v.w - hw);
        }
        {
            const float e0[4] = {wc0.x, wc0.y, wc0.z, wc0.w};
            const float e1[4] = {wc1.x, wc1.y, wc1.z, wc1.w};
            #pragma unroll
            for (int i = 0; i < 4; i++) {
                float h0 = __bfloat162float(__float2bfloat16(e0[i]));
                float h1 = __bfloat162float(__float2bfloat16(e1[i]));
                Bhi[wn4*4 + i][wj] = packbf(h0, h1);
                Blo[wn4*4 + i][wj] = packbf(e0[i] - h0, e1[i] - h1);
            }
        }
        __syncthreads();
        float4 vn[4], wn0, wn1;
        bool more = (kk + 32 < FF);
        if (more) {
            #pragma unroll
            for (int it = 0; it < 4; it++) {
                int f = tid + 256 * it, row = f >> 3, c4 = f & 7;
                vn[it] = make_float4(0.f, 0.f, 0.f, 0.f);
                if (m0 + row < N)
                    vn[it] = *(const float4*)&x[(long long)(m0 + row) * FF + kk + 32 + c4 * 4];
            }
            wn0 = *(const float4*)&W[(kk + 32 + 2 * wj)     * 64 + wn4 * 4];
            wn1 = *(const float4*)&W[(kk + 32 + 2 * wj + 1) * 64 + wn4 * 4];
        }
        #pragma unroll
        for (int sub = 0; sub < 2; sub++) {
            int po = sub * 8;
            uint32_t ah[4], al[4];
            ah[0] = Ahi[wrow + g    ][po + tg];
            ah[1] = Ahi[wrow + g + 8][po + tg];
            ah[2] = Ahi[wrow + g    ][po + tg + 4];
            ah[3] = Ahi[wrow + g + 8][po + tg + 4];
            al[0] = Alo[wrow + g    ][po + tg];
            al[1] = Alo[wrow + g + 8][po + tg];
            al[2] = Alo[wrow + g    ][po + tg + 4];
            al[3] = Alo[wrow + g + 8][po + tg + 4];
            #pragma unroll
            for (int t = 0; t < 8; t++) {
                uint32_t bh[2], bl[2];
                bh[0] = Bhi[t*8 + g][po + tg];
                bh[1] = Bhi[t*8 + g][po + tg + 4];
                bl[0] = Blo[t*8 + g][po + tg];
                bl[1] = Blo[t*8 + g][po + tg + 4];
                mma_bf16(c[t], ah, bh);
                mma_bf16(c[t], ah, bl);
                mma_bf16(c[t], al, bh);
            }
        }
        if (more) {
            #pragma unroll
            for (int it = 0; it < 4; it++) vc[it] = vn[it];
            wc0 = wn0; wc1 = wn1;
        }
    }

    int row0 = m0 + wrow + g;
    int row1 = row0 + 8;
    #pragma unroll
    for (int t = 0; t < 8; t++) {
        if (row0 < N)
            *(float2*)&g_h1[row0 * 64 + t*8 + tg*2] = make_float2(c[t][0], c[t][1]);
        if (row1 < N)
            *(float2*)&g_h1[row1 * 64 + t*8 + tg*2] = make_float2(c[t][2], c[t][3]);
        float as = sA[t*8 + tg*2], as2v = sA[t*8 + tg*2 + 1];
        float ad = sD[t*8 + tg*2], ad2v = sD[t*8 + tg*2 + 1];
        float s0 = c[t][0]*as + c[t][1]*as2v;
        float d0 = c[t][0]*ad + c[t][1]*ad2v;
        float s1 = c[t][2]*as + c[t][3]*as2v;
        float d1 = c[t][2]*ad + c[t][3]*ad2v;
        #pragma unroll
        for (int o = 1; o <= 2; o <<= 1) {
            s0 += __shfl_xor_sync(0xffffffffu, s0, o);
            d0 += __shfl_xor_sync(0xffffffffu, d0, o);
            s1 += __shfl_xor_sync(0xffffffffu, s1, o);
            d1 += __shfl_xor_sync(0xffffffffu, d1, o);
        }
        if (tg == 0) {
            if (row0 < N) { g_as1[row0 * 8 + t] = s0; g_ad1[row0 * 8 + t] = d0; }
            if (row1 < N) { g_as1[row1 * 8 + t] = s1; g_ad1[row1 * 8 + t] = d1; }
        }
    }
}

// -------- aggregation layer 1 (warp per dst, csr software-pipelined) --------
__global__ void k_agg1(const float* __restrict__ b1, int N) {
    int d = (blockIdx.x * blockDim.x + threadIdx.x) >> 5;
    int lane = threadIdx.x & 31;
    if (d >= N) return;
    int beg = g_off[d], end = g_off[d + 1];
    float ad_l = (lane < NH) ? g_ad1[d * NH + lane] : 0.f;
    float accx = 0.f, accy = 0.f, den = 0.f;
    int s = (beg < end) ? g_csr[beg] : 0;
    for (int i = beg; i < end; i++) {
        int snext = (i + 1 < end) ? g_csr[i + 1] : 0;   // prefetch next index
        float w = 0.f;
        if (lane < NH) {
            float e = g_as1[s * NH + lane] + ad_l;
            e = e > 0.f ? e : 0.2f * e;
            w = __expf(e);
            den += w;
        }
        float wl = __shfl_sync(0xffffffffu, w, lane >> 2);
        float2 hv = *(const float2*)&g_h1[s * 64 + lane * 2];
        accx += wl * hv.x;
        accy += wl * hv.y;
        s = snext;
    }
    float denl = __shfl_sync(0xffffffffu, den, lane >> 2);
    float v0 = accx / denl + b1[2 * lane];
    float v1 = accy / denl + b1[2 * lane + 1];
    v0 = v0 > 0.f ? v0 : expm1f(v0);
    v1 = v1 > 0.f ? v1 : expm1f(v1);
    *(float2*)&g_x2[d * 64 + 2 * lane] = make_float2(v0, v1);
}

// -------- GEMM2 + alpha projections layer 2 (padded h2 record) --------------
__global__ void k_gemm2(const float* __restrict__ W2,
                        const float* __restrict__ a_src2,
                        const float* __restrict__ a_dst2, int N) {
    int wid = (blockIdx.x * blockDim.x + threadIdx.x) >> 5;
    int lane = threadIdx.x & 31;
    if (wid >= N) return;
    float v0 = g_x2[wid * 64 + lane];
    float v1 = g_x2[wid * 64 + 32 + lane];
    float asum = 0.f, adsum = 0.f;
    #pragma unroll
    for (int c = 0; c < NC; c++) {
        float s = v0 * W2[lane * NC + c] + v1 * W2[(lane + 32) * NC + c];
        #pragma unroll
        for (int o = 16; o; o >>= 1) s += __shfl_down_sync(0xffffffffu, s, o);
        if (lane == 0) {
            g_h2p[wid * 12 + c] = s;
            asum  += s * a_src2[c];
            adsum += s * a_dst2[c];
        }
    }
    if (lane == 0) {
        g_h2p[wid * 12 + 10] = asum;   // alpha_src packed into the record
        g_h2p[wid * 12 + 11] = 0.f;
        g_ad2[wid] = adsum;
    }
}

// -------- aggregation layer 2 (3x LDG.128 per edge) -------------------------
__global__ void k_agg2(const float* __restrict__ b2, float* __restrict__ out, int N) {
    int d = (blockIdx.x * blockDim.x + threadIdx.x) >> 5;
    int lane = threadIdx.x & 31;
    if (d >= N) return;
    int beg = g_off[d], end = g_off[d + 1];
    float ad_d = g_ad2[d];
    float acc[NC] = {};
    float den = 0.f;
    for (int i = beg + lane; i < end; i += 32) {
        int s = g_csr[i];
        const float4* rp = (const float4*)&g_h2p[s * 12];
        float4 f0 = rp[0], f1 = rp[1], f2 = rp[2];
        float e = f2.z + ad_d;                 // f2.z = a_src2 . h2[s]
        e = e > 0.f ? e : 0.2f * e;
        float w = __expf(e);
        den += w;
        acc[0] += w * f0.x; acc[1] += w * f0.y; acc[2] += w * f0.z; acc[3] += w * f0.w;
        acc[4] += w * f1.x; acc[5] += w * f1.y; acc[6] += w * f1.z; acc[7] += w * f1.w;
        acc[8] += w * f2.x; acc[9] += w * f2.y;
    }
    #pragma unroll
    for (int o = 16; o; o >>= 1) {
        den += __shfl_down_sync(0xffffffffu, den, o);
        #pragma unroll
        for (int c = 0; c < NC; c++)
            acc[c] += __shfl_down_sync(0xffffffffu, acc[c], o);
    }
    if (lane == 0) {
        float inv = 1.f / den;
        float v[NC], m = -1e30f;
        #pragma unroll
        for (int c = 0; c < NC; c++) {
            v[c] = acc[c] * inv + b2[c];
            m = fmaxf(m, v[c]);
        }
        float ssum = 0.f;
        #pragma unroll
        for (int c = 0; c < NC; c++) ssum += __expf(v[c] - m);
        float l = __logf(ssum);
        #pragma unroll
        for (int c = 0; c < NC; c++) out[d * NC + c] = v[c] - m - l;
    }
}

// ---------------------------------------------------------------------------
extern "C" void kernel_launch(void* const* d_in, const int* in_sizes, int n_in,
                              void* d_out, int out_size) {
    const float* x   = (const float*)d_in[0];
    const void*  ei  = d_in[1];
    const float* W1  = (const float*)d_in[2];
    const float* as1 = (const float*)d_in[3];
    const float* ad1 = (const float*)d_in[4];
    const float* b1  = (const float*)d_in[5];
    const float* W2  = (const float*)d_in[6];
    const float* as2 = (const float*)d_in[7];
    const float* ad2 = (const float*)d_in[8];
    const float* b2  = (const float*)d_in[9];

    int       N  = in_sizes[0] / FF;
    long long E  = (long long)in_sizes[1] / 2;
    long long EN = E + (long long)N;
    int nb = (N + SCANB - 1) / SCANB;
    float* out = (float*)d_out;

    cudaStream_t s1 = 0;
    cudaEvent_t ev0 = 0, ev1 = 0;
    bool forked =
        cudaStreamCreateWithFlags(&s1, cudaStreamNonBlocking) == cudaSuccess &&
        cudaEventCreateWithFlags(&ev0, cudaEventDisableTiming) == cudaSuccess &&
        cudaEventCreateWithFlags(&ev1, cudaEventDisableTiming) == cudaSuccess;

    if (forked) forked = cudaEventRecord(ev0, 0) == cudaSuccess &&
                         cudaStreamWaitEvent(s1, ev0, 0) == cudaSuccess;

    cudaStream_t cs = forked ? s1 : 0;

    // ---- branch A: CSR build (edge_index only) ----
    k_zero<<<(N + 255) / 256, 256, 0, cs>>>((const long long*)ei, E, N);
    k_hist<<<(unsigned)((EN + 255) / 256), 256, 0, cs>>>(ei, E, N);
    k_scan1<<<nb, SCANB, 0, cs>>>(N);
    k_scan3<<<nb, SCANB, 0, cs>>>(N, (int)EN, nb);
    k_scatter<<<(unsigned)((EN + 255) / 256), 256, 0, cs>>>(ei, E, N);
    if (forked) forked = cudaEventRecord(ev1, s1) == cudaSuccess;

    // ---- branch B: projection GEMM (x, W1 only) ----
    k_gemm1<<<(N + 127) / 128, 256>>>(x, W1, as1, ad1, N);

    // ---- join + tail ----
    if (forked) cudaStreamWaitEvent(0, ev1, 0);

    k_agg1<<<(unsigned)(((long long)N * 32 + 255) / 256), 256>>>(b1, N);
    k_gemm2<<<(unsigned)(((long long)N * 32 + 255) / 256), 256>>>(W2, as2, ad2, N);
    k_agg2<<<(unsigned)(((long long)N * 32 + 255) / 256), 256>>>(b2, out, N);
    // Streams/events intentionally not destroyed (illegal mid-capture;
    // host-side handles only, O(1) calls, no device memory involved).
}

// round 13
// speedup vs baseline: 1.1527x; 1.0019x over previous
#include <cuda_runtime.h>
#include <cuda_bf16.h>
#include <cstdint>

#define FF  512
#define HD  64
#define NH  8
#define NC  10
#define NMAX 50000
#define EMAX 1700000
#define SCANB 256
#define NBMAX ((NMAX + SCANB - 1) / SCANB)

// -------- scratch (static device globals; no allocation allowed) ----------
static __device__ float g_h1  [NMAX*HD];
static __device__ float g_as1 [NMAX*NH];
static __device__ float g_ad1 [NMAX*NH];
static __device__ float g_h2p [NMAX*12];   // h2[0..9], slot10 = a_src2·h2
static __device__ float g_ad2 [NMAX];
static __device__ int   g_cnt [NMAX];
static __device__ int   g_off [NMAX+1];
static __device__ int   g_cur [NMAX];
static __device__ int   g_csr [EMAX];
static __device__ int   g_bsum[NBMAX];
static __device__ int   g_is32;

__device__ __forceinline__ uint32_t packbf(float lo16, float hi16) {
    uint32_t r;
    asm("cvt.rn.bf16x2.f32 %0, %1, %2;" : "=r"(r) : "f"(hi16), "f"(lo16));
    return r;
}
__device__ __forceinline__ void mma_bf16(float* c, const uint32_t* a, const uint32_t* b) {
    asm volatile(
        "mma.sync.aligned.m16n8k16.row.col.f32.bf16.bf16.f32 "
        "{%0,%1,%2,%3}, {%4,%5,%6,%7}, {%8,%9}, {%0,%1,%2,%3};"
        : "+f"(c[0]), "+f"(c[1]), "+f"(c[2]), "+f"(c[3])
        : "r"(a[0]), "r"(a[1]), "r"(a[2]), "r"(a[3]), "r"(b[0]), "r"(b[1]));
}

// -------- zero + edge dtype sniffer (merged) --------------------------------
__global__ void k_zero(const long long* __restrict__ e, long long E, long long N) {
    int i = blockIdx.x * blockDim.x + threadIdx.x;
    if (i < (int)N) g_cnt[i] = 0;
    if (blockIdx.x == 0 && threadIdx.x == 0) {
        int is32 = 0;
        long long cnt = E < 256 ? E : 256;
        for (long long j = 0; j < cnt; j++) {
            long long v = e[j];
            if (v < 0 || v >= N) { is32 = 1; break; }
        }
        g_is32 = is32;
    }
}

// -------- CSR histogram -----------------------------------------------------
__global__ void k_hist(const void* __restrict__ ei, long long E, int N) {
    long long i = (long long)blockIdx.x * blockDim.x + threadIdx.x;
    long long EN = E + (long long)N;
    if (i >= EN) return;
    int d;
    if (i >= E) d = (int)(i - E);
    else if (g_is32) d = ((const int*)ei)[E + i];
    else             d = (int)((const long long*)ei)[E + i];
    atomicAdd(&g_cnt[d], 1);
}

// -------- scan level 1 ------------------------------------------------------
__global__ void k_scan1(int N) {
    __shared__ int sh[SCANB];
    int t = threadIdx.x;
    int i = blockIdx.x * SCANB + t;
    int v = (i < N) ? g_cnt[i] : 0;
    sh[t] = v;
    __syncthreads();
    #pragma unroll
    for (int o = 1; o < SCANB; o <<= 1) {
        int u = (t >= o) ? sh[t - o] : 0;
        __syncthreads();
        sh[t] += u;
        __syncthreads();
    }
    if (i < N) g_off[i] = sh[t] - v;
    if (t == SCANB - 1) g_bsum[blockIdx.x] = sh[t];
}

// -------- scan level 2+3 merged ---------------------------------------------
__global__ void k_scan3(int N, int total, int nb) {
    __shared__ int sh[SCANB];
    int t = threadIdx.x;
    int v = (t < nb && t < blockIdx.x) ? g_bsum[t] : 0;
    sh[t] = v;
    __syncthreads();
    #pragma unroll
    for (int o = SCANB / 2; o; o >>= 1) {
        if (t < o) sh[t] += sh[t + o];
        __syncthreads();
    }
    int base = sh[0];
    int i = blockIdx.x * SCANB + t;
    if (i < N) {
        int o = g_off[i] + base;
        g_off[i] = o;
        g_cur[i] = o;
    }
    if (i == 0) g_off[N] = total;
}

// -------- CSR scatter -------------------------------------------------------
__global__ void k_scatter(const void* __restrict__ ei, long long E, int N) {
    long long i = (long long)blockIdx.x * blockDim.x + threadIdx.x;
    long long EN = E + (long long)N;
    if (i >= EN) return;
    int s, d;
    if (i >= E) { s = d = (int)(i - E); }
    else if (g_is32) { const int* p = (const int*)ei; s = p[i]; d = p[E + i]; }
    else { const long long* p = (const long long*)ei; s = (int)p[i]; d = (int)p[E + i]; }
    int pos = atomicAdd(&g_cur[d], 1);
    g_csr[pos] = s;
}

// -------- GEMM1 (tensor cores): split-bf16, double-buffered, alpha1 fused ---
__global__ void k_gemm1(const float* __restrict__ x, const float* __restrict__ W,
                        const float* __restrict__ a_src, const float* __restrict__ a_dst,
                        int N) {
    __shared__ uint32_t Ahi[128][20], Alo[128][20];
    __shared__ uint32_t Bhi[64][20],  Blo[64][20];
    __shared__ float sA[64], sD[64];

    int tid  = threadIdx.x;
    int lane = tid & 31;
    int warp = tid >> 5;
    int m0   = blockIdx.x * 128;
    int wrow = warp * 16;
    int g = lane >> 2, tg = lane & 3;

    if (tid < 64) { sA[tid] = a_src[tid]; sD[tid] = a_dst[tid]; }

    float c[8][4] = {};

    float4 vc[4];
    #pragma unroll
    for (int it = 0; it < 4; it++) {
        int f = tid + 256 * it, row = f >> 3, c4 = f & 7;
        vc[it] = make_float4(0.f, 0.f, 0.f, 0.f);
        if (m0 + row < N)
            vc[it] = *(const float4*)&x[(long long)(m0 + row) * FF + c4 * 4];
    }
    int wj = tid >> 4, wn4 = tid & 15;
    float4 wc0 = *(const float4*)&W[(2 * wj)     * 64 + wn4 * 4];
    float4 wc1 = *(const float4*)&W[(2 * wj + 1) * 64 + wn4 * 4];

    for (int kk = 0; kk < FF; kk += 32) {
        __syncthreads();
        #pragma unroll
        for (int it = 0; it < 4; it++) {
            int f = tid + 256 * it, row = f >> 3, c4 = f & 7;
            float4 v = vc[it];
            float hx = __bfloat162float(__float2bfloat16(v.x));
            float hy = __bfloat162float(__float2bfloat16(v.y));
            float hz = __bfloat162float(__float2bfloat16(v.z));
            float hw = __bfloat162float(__float2bfloat16(v.w));
            Ahi[row][c4*2+0] = packbf(hx, hy);
            Ahi[row][c4*2+1] = packbf(hz, hw);
            Alo[row][c4*2+0] = packbf(v.x - hx, v.y - hy);
            Alo[row][c4*2+1] = packbf(v.z - hz, v.w - hw);
        }
        {
            const float e0[4] = {wc0.x, wc0.y, wc0.z, wc0.w};
            const float e1[4] = {wc1.x, wc1.y, wc1.z, wc1.w};
            #pragma unroll
            for (int i = 0; i < 4; i++) {
                float h0 = __bfloat162float(__float2bfloat16(e0[i]));
                float h1 = __bfloat162float(__float2bfloat16(e1[i]));
                Bhi[wn4*4 + i][wj] = packbf(h0, h1);
                Blo[wn4*4 + i][wj] = packbf(e0[i] - h0, e1[i] - h1);
            }
        }
        __syncthreads();
        float4 vn[4], wn0, wn1;
        bool more = (kk + 32 < FF);
        if (more) {
            #pragma unroll
            for (int it = 0; it < 4; it++) {
                int f = tid + 256 * it, row = f >> 3, c4 = f & 7;
                vn[it] = make_float4(0.f, 0.f, 0.f, 0.f);
                if (m0 + row < N)
                    vn[it] = *(const float4*)&x[(long long)(m0 + row) * FF + kk + 32 + c4 * 4];
            }
            wn0 = *(const float4*)&W[(kk + 32 + 2 * wj)     * 64 + wn4 * 4];
            wn1 = *(const float4*)&W[(kk + 32 + 2 * wj + 1) * 64 + wn4 * 4];
        }
        #pragma unroll
        for (int sub = 0; sub < 2; sub++) {
            int po = sub * 8;
            uint32_t ah[4], al[4];
            ah[0] = Ahi[wrow + g    ][po + tg];
            ah[1] = Ahi[wrow + g + 8][po + tg];
            ah[2] = Ahi[wrow + g    ][po + tg + 4];
            ah[3] = Ahi[wrow + g + 8][po + tg + 4];
            al[0] = Alo[wrow + g    ][po + tg];
            al[1] = Alo[wrow + g + 8][po + tg];
            al[2] = Alo[wrow + g    ][po + tg + 4];
            al[3] = Alo[wrow + g + 8][po + tg + 4];
            #pragma unroll
            for (int t = 0; t < 8; t++) {
                uint32_t bh[2], bl[2];
                bh[0] = Bhi[t*8 + g][po + tg];
                bh[1] = Bhi[t*8 + g][po + tg + 4];
                bl[0] = Blo[t*8 + g][po + tg];
                bl[1] = Blo[t*8 + g][po + tg + 4];
                mma_bf16(c[t], ah, bh);
                mma_bf16(c[t], ah, bl);
                mma_bf16(c[t], al, bh);
            }
        }
        if (more) {
            #pragma unroll
            for (int it = 0; it < 4; it++) vc[it] = vn[it];
            wc0 = wn0; wc1 = wn1;
        }
    }

    int row0 = m0 + wrow + g;
    int row1 = row0 + 8;
    #pragma unroll
    for (int t = 0; t < 8; t++) {
        if (row0 < N)
            *(float2*)&g_h1[row0 * 64 + t*8 + tg*2] = make_float2(c[t][0], c[t][1]);
        if (row1 < N)
            *(float2*)&g_h1[row1 * 64 + t*8 + tg*2] = make_float2(c[t][2], c[t][3]);
        float as = sA[t*8 + tg*2], as2v = sA[t*8 + tg*2 + 1];
        float ad = sD[t*8 + tg*2], ad2v = sD[t*8 + tg*2 + 1];
        float s0 = c[t][0]*as + c[t][1]*as2v;
        float d0 = c[t][0]*ad + c[t][1]*ad2v;
        float s1 = c[t][2]*as + c[t][3]*as2v;
        float d1 = c[t][2]*ad + c[t][3]*ad2v;
        #pragma unroll
        for (int o = 1; o <= 2; o <<= 1) {
            s0 += __shfl_xor_sync(0xffffffffu, s0, o);
            d0 += __shfl_xor_sync(0xffffffffu, d0, o);
            s1 += __shfl_xor_sync(0xffffffffu, s1, o);
            d1 += __shfl_xor_sync(0xffffffffu, d1, o);
        }
        if (tg == 0) {
            if (row0 < N) { g_as1[row0 * 8 + t] = s0; g_ad1[row0 * 8 + t] = d0; }
            if (row1 < N) { g_as1[row1 * 8 + t] = s1; g_ad1[row1 * 8 + t] = d1; }
        }
    }
}

// -------- agg layer 1 + GEMM2 + alpha2, fused (smem-staged W2) --------------
// Warp per dst. The gather loop is unchanged (no extra live registers);
// the 64->10 projection reads W2 from shared AFTER the loop exits.
__global__ void k_agg1(const float* __restrict__ b1,
                       const float* __restrict__ W2,
                       const float* __restrict__ a_src2,
                       const float* __restrict__ a_dst2, int N) {
    __shared__ float sW2[HD * NC];    // 2.5 KB, [f*10+c]
    __shared__ float sAs2[NC], sAd2[NC], sB1[HD];
    int tid = threadIdx.x;
    for (int i = tid; i < HD * NC; i += blockDim.x) sW2[i] = W2[i];
    if (tid < NC) { sAs2[tid] = a_src2[tid]; sAd2[tid] = a_dst2[tid]; }
    if (tid < HD) sB1[tid] = b1[tid];
    __syncthreads();

    int d = (blockIdx.x * blockDim.x + tid) >> 5;
    int lane = tid & 31;
    if (d >= N) return;
    int beg = g_off[d], end = g_off[d + 1];
    float ad_l = (lane < NH) ? g_ad1[d * NH + lane] : 0.f;
    float accx = 0.f, accy = 0.f, den = 0.f;
    int s = (beg < end) ? g_csr[beg] : 0;
    for (int i = beg; i < end; i++) {
        int snext = (i + 1 < end) ? g_csr[i + 1] : 0;
        float w = 0.f;
        if (lane < NH) {
            float e = g_as1[s * NH + lane] + ad_l;
            e = e > 0.f ? e : 0.2f * e;
            w = __expf(e);
            den += w;
        }
        float wl = __shfl_sync(0xffffffffu, w, lane >> 2);
        float2 hv = *(const float2*)&g_h1[s * 64 + lane * 2];
        accx += wl * hv.x;
        accy += wl * hv.y;
        s = snext;
    }
    float denl = __shfl_sync(0xffffffffu, den, lane >> 2);
    float v0 = accx / denl + sB1[2 * lane];
    float v1 = accy / denl + sB1[2 * lane + 1];
    v0 = v0 > 0.f ? v0 : expm1f(v0);   // ELU
    v1 = v1 > 0.f ? v1 : expm1f(v1);

    // fused 64->10 projection + alpha2 (lane covers features 2*lane, 2*lane+1)
    float asum = 0.f, adsum = 0.f;
    #pragma unroll
    for (int c = 0; c < NC; c++) {
        float sacc = v0 * sW2[(2 * lane) * NC + c] + v1 * sW2[(2 * lane + 1) * NC + c];
        #pragma unroll
        for (int o = 16; o; o >>= 1) sacc += __shfl_down_sync(0xffffffffu, sacc, o);
        if (lane == 0) {
            g_h2p[d * 12 + c] = sacc;
            asum  += sacc * sAs2[c];
            adsum += sacc * sAd2[c];
        }
    }
    if (lane == 0) {
        g_h2p[d * 12 + 10] = asum;
        g_h2p[d * 12 + 11] = 0.f;
        g_ad2[d] = adsum;
    }
}

// -------- aggregation layer 2 (3x LDG.128/edge, index pipelined) -------------
__global__ void k_agg2(const float* __restrict__ b2, float* __restrict__ out, int N) {
    int d = (blockIdx.x * blockDim.x + threadIdx.x) >> 5;
    int lane = threadIdx.x & 31;
    if (d >= N) return;
    int beg = g_off[d], end = g_off[d + 1];
    float ad_d = g_ad2[d];
    float acc[NC] = {};
    float den = 0.f;
    int i = beg + lane;
    int s = (i < end) ? g_csr[i] : 0;
    for (; i < end; i += 32) {
        int snext = (i + 32 < end) ? g_csr[i + 32] : 0;
        const float4* rp = (const float4*)&g_h2p[s * 12];
        float4 f0 = rp[0], f1 = rp[1], f2 = rp[2];
        float e = f2.z + ad_d;                 // f2.z = a_src2 . h2[s]
        e = e > 0.f ? e : 0.2f * e;
        float w = __expf(e);
        den += w;
        acc[0] += w * f0.x; acc[1] += w * f0.y; acc[2] += w * f0.z; acc[3] += w * f0.w;
        acc[4] += w * f1.x; acc[5] += w * f1.y; acc[6] += w * f1.z; acc[7] += w * f1.w;
        acc[8] += w * f2.x; acc[9] += w * f2.y;
        s = snext;
    }
    #pragma unroll
    for (int o = 16; o; o >>= 1) {
        den += __shfl_down_sync(0xffffffffu, den, o);
        #pragma unroll
        for (int c = 0; c < NC; c++)
            acc[c] += __shfl_down_sync(0xffffffffu, acc[c], o);
    }
    if (lane == 0) {
        float inv = 1.f / den;
        float v[NC], m = -1e30f;
        #pragma unroll
        for (int c = 0; c < NC; c++) {
            v[c] = acc[c] * inv + b2[c];
            m = fmaxf(m, v[c]);
        }
        float ssum = 0.f;
        #pragma unroll
        for (int c = 0; c < NC; c++) ssum += __expf(v[c] - m);
        float l = __logf(ssum);
        #pragma unroll
        for (int c = 0; c < NC; c++) out[d * NC + c] = v[c] - m - l;
    }
}

// ---------------------------------------------------------------------------
extern "C" void kernel_launch(void* const* d_in, const int* in_sizes, int n_in,
                              void* d_out, int out_size) {
    const float* x   = (const float*)d_in[0];
    const void*  ei  = d_in[1];
    const float* W1  = (const float*)d_in[2];
    const float* as1 = (const float*)d_in[3];
    const float* ad1 = (const float*)d_in[4];
    const float* b1  = (const float*)d_in[5];
    const float* W2  = (const float*)d_in[6];
    const float* as2 = (const float*)d_in[7];
    const float* ad2 = (const float*)d_in[8];
    const float* b2  = (const float*)d_in[9];

    int       N  = in_sizes[0] / FF;
    long long E  = (long long)in_sizes[1] / 2;
    long long EN = E + (long long)N;
    int nb = (N + SCANB - 1) / SCANB;
    float* out = (float*)d_out;

    cudaStream_t s1 = 0;
    cudaEvent_t ev0 = 0, ev1 = 0;
    bool forked =
        cudaStreamCreateWithFlags(&s1, cudaStreamNonBlocking) == cudaSuccess &&
        cudaEventCreateWithFlags(&ev0, cudaEventDisableTiming) == cudaSuccess &&
        cudaEventCreateWithFlags(&ev1, cudaEventDisableTiming) == cudaSuccess;

    if (forked) forked = cudaEventRecord(ev0, 0) == cudaSuccess &&
                         cudaStreamWaitEvent(s1, ev0, 0) == cudaSuccess;

    cudaStream_t cs = forked ? s1 : 0;

    // ---- branch A: CSR build (edge_index only) ----
    k_zero<<<(N + 255) / 256, 256, 0, cs>>>((const long long*)ei, E, N);
    k_hist<<<(unsigned)((EN + 255) / 256), 256, 0, cs>>>(ei, E, N);
    k_scan1<<<nb, SCANB, 0, cs>>>(N);
    k_scan3<<<nb, SCANB, 0, cs>>>(N, (int)EN, nb);
    k_scatter<<<(unsigned)((EN + 255) / 256), 256, 0, cs>>>(ei, E, N);
    if (forked) forked = cudaEventRecord(ev1, s1) == cudaSuccess;

    // ---- branch B: projection GEMM (x, W1 only) ----
    k_gemm1<<<(N + 127) / 128, 256>>>(x, W1, as1, ad1, N);

    // ---- join + tail ----
    if (forked) cudaStreamWaitEvent(0, ev1, 0);

    k_agg1<<<(unsigned)(((long long)N * 32 + 255) / 256), 256>>>(b1, W2, as2, ad2, N);
    k_agg2<<<(unsigned)(((long long)N * 32 + 255) / 256), 256>>>(b2, out, N);
    // Streams/events intentionally not destroyed (illegal mid-capture;
    // host-side handles only, O(1) calls, no device memory involved).
}